// round 9
// baseline (speedup 1.0000x reference)
#include <cuda_runtime.h>

#define NL 50
#define THREADS 1024

// Edge integers: E_i = i for i<=25, else 25 + 7*(i-25); E_50 = 200.
// Edge floats computed exactly as numpy: (double)n / 200.0 * 0.6, cast to f32.
constexpr int   edge_int(int i) { return i <= 25 ? i : 25 + 7 * (i - 25); }
constexpr float edge_f(int i)   { return (float)((double)edge_int(i) / 200.0 * 0.6); }

#define E1(a)  edge_f(a)
#define E4(a)  E1(a), E1(a+1), E1(a+2), E1(a+3)
#define E16(a) E4(a), E4(a+4), E4(a+8), E4(a+12)
__constant__ float c_edges[51] = { E16(0), E16(16), E16(32), E1(48), E1(49), E1(50) };

// tbl2[c] = {E_c, E_{c+1}} (LDS.64). wext[j+1] = w_j zero-padded:
// wext[0] = wext[51] = 0. Fully branchless bin lookup.
__device__ __forceinline__ float bin_weight(float z,
                                            const float2* __restrict__ tbl2,
                                            const float*  __restrict__ wext)
{
    float t = z * (200.0f / 0.6f);
    int ci  = (int)t;
    int ci2 = 25 + (int)((t - 25.0f) * (1.0f / 7.0f));
    int c   = (t < 25.0f) ? ci : ci2;
    c = min(max(c, 0), NL - 1);

    float2 e = tbl2[c];                       // LDS.64: {lo, hi}
    bool in  = (z > e.x) & (z < e.y);
    int  j   = (z >= e.y) ? c + 1 : c - 1;    // off-by-one fallback bin
    bool out = (z >= 0.6f) | (z <= 0.0f);     // outside all bins
    int  k   = out ? 51 : ((in ? c : j) + 1); // wext[51] == 0
    return wext[k];                           // LDS.32
}

__global__ __launch_bounds__(THREADS) void zws_kernel(
    const float4* __restrict__ x,      // (B, V/2) float4 = 2 (z,val) pairs
    const float*  __restrict__ weight, // (NL,)
    const float*  __restrict__ bias,   // (NL,)
    float*        __restrict__ out,    // (B,)
    int nf4_per_row)                   // V/2 (= 2048)
{
    __shared__ float2 tbl2[NL];
    __shared__ float  wext[NL + 2];
    __shared__ float  red[THREADS / 32];

    const int tid = threadIdx.x;
    const int b   = blockIdx.x;

    const float4* row = x + (size_t)b * nf4_per_row;

    // ---- Issue bulk data loads FIRST (independent of the table) ----
    const int i0 = tid;
    const int i1 = tid + THREADS;
    float4 p0 = make_float4(0.f, 0.f, 0.f, 0.f);
    float4 p1 = make_float4(0.f, 0.f, 0.f, 0.f);
    if (i0 < nf4_per_row) p0 = __ldg(&row[i0]);
    if (i1 < nf4_per_row) p1 = __ldg(&row[i1]);

    // ---- Table setup overlaps the DRAM latency of p0/p1 ----
    float acc = 0.0f;
    if (tid < NL) {
        float w = weight[tid];
        tbl2[tid]     = make_float2(c_edges[tid], c_edges[tid + 1]);
        wext[tid + 1] = w;
        acc = bias[tid] * w;                       // fold dot(bias, weight)
    }
    if (tid == 0) { wext[0] = 0.0f; wext[NL + 1] = 0.0f; }
    __syncthreads();

    acc = fmaf(p0.y, bin_weight(p0.x, tbl2, wext), acc);
    acc = fmaf(p0.w, bin_weight(p0.z, tbl2, wext), acc);
    acc = fmaf(p1.y, bin_weight(p1.x, tbl2, wext), acc);
    acc = fmaf(p1.w, bin_weight(p1.z, tbl2, wext), acc);

    // Tail for nonstandard shapes (not executed for V=4096).
    for (int i = i1 + THREADS; i < nf4_per_row; i += THREADS) {
        float4 p = __ldg(&row[i]);
        acc = fmaf(p.y, bin_weight(p.x, tbl2, wext), acc);
        acc = fmaf(p.w, bin_weight(p.z, tbl2, wext), acc);
    }

    // ---- Block reduction (32 warps) ----
    #pragma unroll
    for (int o = 16; o; o >>= 1)
        acc += __shfl_down_sync(0xFFFFFFFFu, acc, o);

    if ((tid & 31) == 0) red[tid >> 5] = acc;
    __syncthreads();

    if (tid < 32) {
        float v = red[tid];
        #pragma unroll
        for (int o = 16; o; o >>= 1)
            v += __shfl_down_sync(0xFFFFFFFFu, v, o);
        if (tid == 0) out[b] = v;
    }
}

extern "C" void kernel_launch(void* const* d_in, const int* in_sizes, int n_in,
                              void* d_out, int out_size)
{
    const float4* x      = (const float4*)d_in[0];  // (B, V, 2) float32
    const float*  weight = (const float*)d_in[1];   // (NL, 1)
    const float*  bias   = (const float*)d_in[2];   // (NL,)
    float*        out    = (float*)d_out;           // (B,)

    const int B = out_size;                          // 256
    const int pairs_total = in_sizes[0] / 2;         // B * V
    const int nf4_per_row = pairs_total / B / 2;     // V / 2 = 2048

    zws_kernel<<<B, THREADS>>>(x, weight, bias, out, nf4_per_row);
}

// round 10
// speedup vs baseline: 1.3527x; 1.3527x over previous
#include <cuda_runtime.h>

#define NL 50
#define THREADS 1024

// Edge integers: E_i = i for i<=25, else 25 + 7*(i-25); E_50 = 200.
// Edge floats computed exactly as numpy: (double)n / 200.0 * 0.6, cast to f32.
constexpr int   edge_int(int i) { return i <= 25 ? i : 25 + 7 * (i - 25); }
constexpr float edge_f(int i)   { return (float)((double)edge_int(i) / 200.0 * 0.6); }

#define E1(a)  edge_f(a)
#define E4(a)  E1(a), E1(a+1), E1(a+2), E1(a+3)
#define E16(a) E4(a), E4(a+4), E4(a+8), E4(a+12)
__constant__ float c_edges[51] = { E16(0), E16(16), E16(32), E1(48), E1(49), E1(50) };

// tbl2[c] = {E_c, E_{c+1}} (LDS.64). wext[j+1] = w_j zero-padded:
// wext[0] = wext[51] = 0 (sentinels absorb z<=0, z>=0.6, and off-by-one).
// Single F2I; /7 via exact integer magic ((x*2341)>>14, exact for x<5461).
// The candidate c may be off by one from float rounding; the open-interval
// compare + j-fallback resolves it exactly, and the sentinels make any
// out-of-range fall-through return weight 0 with no extra checks.
__device__ __forceinline__ float bin_weight(float z,
                                            const float2* __restrict__ tbl2,
                                            const float*  __restrict__ wext)
{
    float t  = z * (200.0f / 0.6f);            // z<=1 -> t<=334, safe
    int   it = (int)t;                          // single F2I (round toward 0)
    it = min(max(it, 0), 199);
    int   c  = (it < 25) ? it : 25 + (((it - 25) * 2341) >> 14);

    float2 e = tbl2[c];                         // LDS.64: {lo, hi}
    bool in  = (z > e.x) & (z < e.y);
    int  j   = (z >= e.y) ? c + 1 : c - 1;      // j in [-1, 50]
    int  k   = (in ? c : j) + 1;                // k in [0, 51]
    return wext[k];                             // LDS.32 (sentinels = 0)
}

__global__ __launch_bounds__(THREADS) void zws_kernel(
    const float4* __restrict__ x,      // (B, V/2) float4 = 2 (z,val) pairs
    const float*  __restrict__ weight, // (NL,)
    const float*  __restrict__ bias,   // (NL,)
    float*        __restrict__ out,    // (B,)
    int nf4_per_row)                   // V/2 (= 2048)
{
    __shared__ float2 tbl2[NL];
    __shared__ float  wext[NL + 2];
    __shared__ float  red[THREADS / 32];

    const int tid = threadIdx.x;
    const int b   = blockIdx.x;

    const float4* row = x + (size_t)b * nf4_per_row;

    // ---- Issue bulk data loads FIRST (independent of the table) ----
    const int i0 = tid;
    const int i1 = tid + THREADS;
    float4 p0 = make_float4(0.f, 0.f, 0.f, 0.f);
    float4 p1 = make_float4(0.f, 0.f, 0.f, 0.f);
    if (i0 < nf4_per_row) p0 = __ldg(&row[i0]);
    if (i1 < nf4_per_row) p1 = __ldg(&row[i1]);

    // ---- Table setup overlaps the DRAM latency of p0/p1 ----
    float acc = 0.0f;
    if (tid < NL) {
        float w = weight[tid];
        tbl2[tid]     = make_float2(c_edges[tid], c_edges[tid + 1]);
        wext[tid + 1] = w;
        acc = bias[tid] * w;                       // fold dot(bias, weight)
    }
    if (tid == 0) { wext[0] = 0.0f; wext[NL + 1] = 0.0f; }
    __syncthreads();

    acc = fmaf(p0.y, bin_weight(p0.x, tbl2, wext), acc);
    acc = fmaf(p0.w, bin_weight(p0.z, tbl2, wext), acc);
    acc = fmaf(p1.y, bin_weight(p1.x, tbl2, wext), acc);
    acc = fmaf(p1.w, bin_weight(p1.z, tbl2, wext), acc);

    // Tail for nonstandard shapes (not executed for V=4096).
    for (int i = i1 + THREADS; i < nf4_per_row; i += THREADS) {
        float4 p = __ldg(&row[i]);
        acc = fmaf(p.y, bin_weight(p.x, tbl2, wext), acc);
        acc = fmaf(p.w, bin_weight(p.z, tbl2, wext), acc);
    }

    // ---- Block reduction (32 warps) ----
    #pragma unroll
    for (int o = 16; o; o >>= 1)
        acc += __shfl_down_sync(0xFFFFFFFFu, acc, o);

    if ((tid & 31) == 0) red[tid >> 5] = acc;
    __syncthreads();

    if (tid < 32) {
        float v = red[tid];
        #pragma unroll
        for (int o = 16; o; o >>= 1)
            v += __shfl_down_sync(0xFFFFFFFFu, v, o);
        if (tid == 0) out[b] = v;
    }
}

extern "C" void kernel_launch(void* const* d_in, const int* in_sizes, int n_in,
                              void* d_out, int out_size)
{
    const float4* x      = (const float4*)d_in[0];  // (B, V, 2) float32
    const float*  weight = (const float*)d_in[1];   // (NL, 1)
    const float*  bias   = (const float*)d_in[2];   // (NL,)
    float*        out    = (float*)d_out;           // (B,)

    const int B = out_size;                          // 256
    const int pairs_total = in_sizes[0] / 2;         // B * V
    const int nf4_per_row = pairs_total / B / 2;     // V / 2 = 2048

    zws_kernel<<<B, THREADS>>>(x, weight, bias, out, nf4_per_row);
}